// round 1
// baseline (speedup 1.0000x reference)
#include <cuda_runtime.h>
#include <cuda_bf16.h>

// Problem dims (fixed by the reference):
//   x: (8192, 512)  weight: (512, 2048)  centers: (2048, 512)  out: (8192, 2048)
#define B_DIM 8192
#define I_DIM 512
#define C_DIM 2048

// Scratch (allocation-free rule: __device__ globals)
__device__ float g_b1[I_DIM * C_DIM];   // w^2                      (I, C)
__device__ float g_b2[I_DIM * C_DIM];   // -2 * w^2 * centers[c,i]  (I, C)
__device__ float g_t3p[16 * C_DIM];     // per-i-chunk partial t3
__device__ float g_t3[C_DIM];           // t3[c] = sum_i w^2 * centers^2

// ---------------------------------------------------------------------------
// prep: build B1, B2 and per-tile t3 partials.
// Grid: (I_DIM/32, C_DIM/32) = (16, 64), block (32, 8).
// centers is read coalesced (i fastest) into smem, weight read coalesced
// (c fastest); b1/b2 written coalesced (c fastest). Deterministic (no atomics).
// ---------------------------------------------------------------------------
__global__ void prep_kernel(const float* __restrict__ weight,
                            const float* __restrict__ centers) {
    __shared__ float sC[32][33];    // sC[cc][ii] = centers[c0+cc][i0+ii]
    __shared__ float sRed[8][33];

    const int i0 = blockIdx.x * 32;
    const int c0 = blockIdx.y * 32;
    const int tx = threadIdx.x;     // 0..31
    const int ty = threadIdx.y;     // 0..7

    // coalesced centers tile load (i contiguous)
    #pragma unroll
    for (int cc = ty; cc < 32; cc += 8)
        sC[cc][tx] = centers[(c0 + cc) * I_DIM + i0 + tx];
    __syncthreads();

    float t3acc = 0.0f;
    #pragma unroll
    for (int ii = ty; ii < 32; ii += 8) {
        const int i = i0 + ii;
        const int gidx = i * C_DIM + c0 + tx;
        float w  = weight[gidx];
        float w2 = w * w;
        float ce = sC[tx][ii];              // centers[c0+tx][i]
        g_b1[gidx] = w2;
        g_b2[gidx] = -2.0f * w2 * ce;
        t3acc += w2 * ce * ce;
    }

    sRed[ty][tx] = t3acc;
    __syncthreads();
    if (ty == 0) {
        float s = 0.0f;
        #pragma unroll
        for (int y = 0; y < 8; y++) s += sRed[y][tx];
        g_t3p[blockIdx.x * C_DIM + c0 + tx] = s;
    }
}

__global__ void t3_reduce_kernel() {
    int c = blockIdx.x * blockDim.x + threadIdx.x;
    if (c < C_DIM) {
        float s = 0.0f;
        #pragma unroll
        for (int p = 0; p < 16; p++) s += g_t3p[p * C_DIM + c];
        g_t3[c] = s;
    }
}

// ---------------------------------------------------------------------------
// Fused dual-GEMM: out[b,c] = sum_k x^2[b,k]*B1[k,c] + x[b,k]*B2[k,c] + t3[c]
// 128x128 block tile, BK=16, 8x8 per-thread microtile, 256 threads.
// ---------------------------------------------------------------------------
#define BM 128
#define BN 128
#define BK 16
#define TM 8
#define TN 8

__global__ __launch_bounds__(256, 2)
void rbf_gemm_kernel(const float* __restrict__ x, float* __restrict__ out) {
    __shared__ float As [BK][BM];   // x tile, transposed for conflict-free reads
    __shared__ float B1s[BK][BN];
    __shared__ float B2s[BK][BN];

    const int tid = threadIdx.x;
    const int block_row = blockIdx.y * BM;
    const int block_col = blockIdx.x * BN;

    const int tr = (tid / 16) * TM;   // row offset within block tile
    const int tc = (tid % 16) * TN;   // col offset within block tile

    const float* xA  = x + block_row * I_DIM;
    const float* B1p = g_b1 + block_col;
    const float* B2p = g_b2 + block_col;

    float acc[TM][TN];
    #pragma unroll
    for (int i = 0; i < TM; i++)
        #pragma unroll
        for (int j = 0; j < TN; j++) acc[i][j] = 0.0f;

    for (int k0 = 0; k0 < I_DIM; k0 += BK) {
        // --- load A tile (128 x 16), store transposed As[k][m]
        #pragma unroll
        for (int l = 0; l < 2; l++) {
            int f  = tid + l * 256;          // float4 index in [0,512)
            int r  = f >> 2;                 // row 0..127
            int c4 = (f & 3) * 4;            // k-col 0,4,8,12
            float4 v = *reinterpret_cast<const float4*>(xA + r * I_DIM + k0 + c4);
            As[c4 + 0][r] = v.x;
            As[c4 + 1][r] = v.y;
            As[c4 + 2][r] = v.z;
            As[c4 + 3][r] = v.w;
        }
        // --- load B1/B2 tiles (16 x 128)
        #pragma unroll
        for (int l = 0; l < 2; l++) {
            int f  = tid + l * 256;          // float4 index in [0,512)
            int r  = f >> 5;                 // k-row 0..15
            int c4 = (f & 31) * 4;           // col 0..124
            *reinterpret_cast<float4*>(&B1s[r][c4]) =
                *reinterpret_cast<const float4*>(B1p + (k0 + r) * C_DIM + c4);
            *reinterpret_cast<float4*>(&B2s[r][c4]) =
                *reinterpret_cast<const float4*>(B2p + (k0 + r) * C_DIM + c4);
        }
        __syncthreads();

        #pragma unroll
        for (int k = 0; k < BK; k++) {
            float a_reg[TM], a2_reg[TM], b1_reg[TN], b2_reg[TN];
            float4 av0 = *reinterpret_cast<const float4*>(&As[k][tr]);
            float4 av1 = *reinterpret_cast<const float4*>(&As[k][tr + 4]);
            a_reg[0] = av0.x; a_reg[1] = av0.y; a_reg[2] = av0.z; a_reg[3] = av0.w;
            a_reg[4] = av1.x; a_reg[5] = av1.y; a_reg[6] = av1.z; a_reg[7] = av1.w;
            #pragma unroll
            for (int i = 0; i < TM; i++) a2_reg[i] = a_reg[i] * a_reg[i];

            float4 b10 = *reinterpret_cast<const float4*>(&B1s[k][tc]);
            float4 b11 = *reinterpret_cast<const float4*>(&B1s[k][tc + 4]);
            b1_reg[0] = b10.x; b1_reg[1] = b10.y; b1_reg[2] = b10.z; b1_reg[3] = b10.w;
            b1_reg[4] = b11.x; b1_reg[5] = b11.y; b1_reg[6] = b11.z; b1_reg[7] = b11.w;

            float4 b20 = *reinterpret_cast<const float4*>(&B2s[k][tc]);
            float4 b21 = *reinterpret_cast<const float4*>(&B2s[k][tc + 4]);
            b2_reg[0] = b20.x; b2_reg[1] = b20.y; b2_reg[2] = b20.z; b2_reg[3] = b20.w;
            b2_reg[4] = b21.x; b2_reg[5] = b21.y; b2_reg[6] = b21.z; b2_reg[7] = b21.w;

            #pragma unroll
            for (int i = 0; i < TM; i++)
                #pragma unroll
                for (int j = 0; j < TN; j++)
                    acc[i][j] += a2_reg[i] * b1_reg[j] + a_reg[i] * b2_reg[j];
        }
        __syncthreads();
    }

    // epilogue: + t3[c], vectorized stores
    float t3r[TN];
    #pragma unroll
    for (int j = 0; j < TN; j++) t3r[j] = g_t3[block_col + tc + j];

    #pragma unroll
    for (int i = 0; i < TM; i++) {
        const int row = block_row + tr + i;
        #pragma unroll
        for (int j = 0; j < TN; j += 4) {
            float4 v;
            v.x = acc[i][j + 0] + t3r[j + 0];
            v.y = acc[i][j + 1] + t3r[j + 1];
            v.z = acc[i][j + 2] + t3r[j + 2];
            v.w = acc[i][j + 3] + t3r[j + 3];
            *reinterpret_cast<float4*>(out + row * C_DIM + block_col + tc + j) = v;
        }
    }
}

// ---------------------------------------------------------------------------
extern "C" void kernel_launch(void* const* d_in, const int* in_sizes, int n_in,
                              void* d_out, int out_size) {
    const float* x       = (const float*)d_in[0];   // (8192, 512)
    const float* weight  = (const float*)d_in[1];   // (512, 2048)
    const float* centers = (const float*)d_in[2];   // (2048, 512)
    float* out = (float*)d_out;                     // (8192, 2048)

    dim3 pgrid(I_DIM / 32, C_DIM / 32);  // (16, 64)
    dim3 pblk(32, 8);
    prep_kernel<<<pgrid, pblk>>>(weight, centers);

    t3_reduce_kernel<<<(C_DIM + 255) / 256, 256>>>();

    dim3 ggrid(C_DIM / BN, B_DIM / BM);  // (16, 64)
    rbf_gemm_kernel<<<ggrid, 256>>>(x, out);
}

// round 3
// speedup vs baseline: 3.9115x; 3.9115x over previous
#include <cuda_runtime.h>
#include <cstdint>

#define B_DIM 8192
#define I_DIM 512
#define C_DIM 2048
#define K_TOT 1024          // concatenated K: [x^2 | x]

#define BM 128
#define BN 128
#define BK 32
#define NITER (K_TOT / BK)          // 32
#define NSTAGE 3
#define A_PAD 36                    // floats per smem row (32 + 4 pad)
#define STAGE_BYTES (2 * BM * A_PAD * 4)   // A + B tile per stage = 36864
#define B_IN_STAGE (BM * A_PAD * 4)        // 18432

// ---------------- device scratch (no allocs allowed) ----------------
__device__ float g_a [B_DIM * K_TOT];   // [tf32(x^2) | tf32(x)]  (8192, 1024)
__device__ float g_bt[C_DIM * K_TOT];   // [tf32(w^2) | tf32(-2 w^2 c)] per center row
__device__ float g_t3p[16 * C_DIM];
__device__ float g_t3[C_DIM];

// ---------------- helpers ----------------
__device__ __forceinline__ uint32_t smem_u32(const void* p) {
    uint32_t a;
    asm("{ .reg .u64 t; cvta.to.shared.u64 t, %1; cvt.u32.u64 %0, t; }" : "=r"(a) : "l"(p));
    return a;
}
__device__ __forceinline__ uint32_t f2tf32(float f) {
    uint32_t r; asm("cvt.rna.tf32.f32 %0, %1;" : "=r"(r) : "f"(f)); return r;
}
__device__ __forceinline__ void cp_async16(uint32_t saddr, const void* gaddr) {
    asm volatile("cp.async.cg.shared.global [%0], [%1], 16;" :: "r"(saddr), "l"(gaddr));
}
__device__ __forceinline__ void cp_commit() {
    asm volatile("cp.async.commit_group;" ::: "memory");
}
__device__ __forceinline__ void cp_wait2() {
    asm volatile("cp.async.wait_group 2;" ::: "memory");
}

__device__ __forceinline__ void mma_tf32(float* d, const uint32_t* a, uint32_t b0, uint32_t b1) {
    asm volatile(
        "mma.sync.aligned.m16n8k8.row.col.f32.tf32.tf32.f32 "
        "{%0,%1,%2,%3}, {%4,%5,%6,%7}, {%8,%9}, {%0,%1,%2,%3};"
        : "+f"(d[0]), "+f"(d[1]), "+f"(d[2]), "+f"(d[3])
        : "r"(a[0]), "r"(a[1]), "r"(a[2]), "r"(a[3]), "r"(b0), "r"(b1));
}

// ---------------------------------------------------------------------------
// prep_w: g_bt[c][k] = tf32(w^2) | tf32(-2 w^2 centers), + t3 partials.
// grid (16, 64), block (32, 8).
// ---------------------------------------------------------------------------
__global__ void prep_w_kernel(const float* __restrict__ weight,
                              const float* __restrict__ centers) {
    __shared__ float sW[32][33];
    __shared__ float sC[32][33];

    const int i0 = blockIdx.x * 32;
    const int c0 = blockIdx.y * 32;
    const int tx = threadIdx.x;
    const int ty = threadIdx.y;

    #pragma unroll
    for (int ii = ty; ii < 32; ii += 8)
        sW[ii][tx] = weight[(i0 + ii) * C_DIM + c0 + tx];
    #pragma unroll
    for (int cc = ty; cc < 32; cc += 8)
        sC[cc][tx] = centers[(c0 + cc) * I_DIM + i0 + tx];
    __syncthreads();

    #pragma unroll
    for (int cc = ty; cc < 32; cc += 8) {
        float w  = sW[tx][cc];      // weight[i0+tx][c0+cc]
        float w2 = w * w;
        float ce = sC[cc][tx];      // centers[c0+cc][i0+tx]
        float* row = g_bt + (size_t)(c0 + cc) * K_TOT;
        row[i0 + tx]         = __uint_as_float(f2tf32(w2));
        row[I_DIM + i0 + tx] = __uint_as_float(f2tf32(-2.0f * w2 * ce));
        float v = w2 * ce * ce;     // exact fp32 t3 partial
        #pragma unroll
        for (int d = 16; d > 0; d >>= 1)
            v += __shfl_xor_sync(0xFFFFFFFF, v, d);
        if (tx == 0) g_t3p[blockIdx.x * C_DIM + c0 + cc] = v;
    }
}

__global__ void t3_reduce_kernel() {
    int c = blockIdx.x * blockDim.x + threadIdx.x;
    if (c < C_DIM) {
        float s = 0.0f;
        #pragma unroll
        for (int p = 0; p < 16; p++) s += g_t3p[p * C_DIM + c];
        g_t3[c] = s;
    }
}

// ---------------------------------------------------------------------------
// prep_x: g_a[b][0:512] = tf32(x^2), g_a[b][512:1024] = tf32(x). grid 4096x256.
// ---------------------------------------------------------------------------
__global__ void prep_x_kernel(const float* __restrict__ x) {
    int f = blockIdx.x * blockDim.x + threadIdx.x;   // float4 id, [0, 1M)
    int r  = f >> 7;                                 // row 0..8191
    int c4 = (f & 127) << 2;                         // col 0..508
    float4 v = *reinterpret_cast<const float4*>(x + (size_t)r * I_DIM + c4);
    uint4 sq, rw;
    sq.x = f2tf32(v.x * v.x); sq.y = f2tf32(v.y * v.y);
    sq.z = f2tf32(v.z * v.z); sq.w = f2tf32(v.w * v.w);
    rw.x = f2tf32(v.x); rw.y = f2tf32(v.y); rw.z = f2tf32(v.z); rw.w = f2tf32(v.w);
    *reinterpret_cast<uint4*>(g_a + (size_t)r * K_TOT + c4)         = sq;
    *reinterpret_cast<uint4*>(g_a + (size_t)r * K_TOT + I_DIM + c4) = rw;
}

// ---------------------------------------------------------------------------
// GEMM: out = g_a @ g_bt^T + t3.  128x128x32 tiles, 3-stage cp.async,
// 8 warps (4x2), warp tile 32x64, mma.sync m16n8k8 tf32.
// ---------------------------------------------------------------------------
__global__ __launch_bounds__(256, 2)
void rbf_mma_gemm(float* __restrict__ out) {
    extern __shared__ char smem[];
    const uint32_t sbase = smem_u32(smem);

    const int tid = threadIdx.x;
    const int wid = tid >> 5;
    const int lid = tid & 31;
    const int g   = lid >> 2;       // groupID 0..7
    const int tg  = lid & 3;        // thread-in-group 0..3
    const int wm  = wid >> 1;       // 0..3  -> m offset wm*32
    const int wn  = wid & 1;        // 0..1  -> n offset wn*64

    const int block_row = blockIdx.y * BM;
    const int block_col = blockIdx.x * BN;
    const float* gA = g_a  + (size_t)block_row * K_TOT;
    const float* gB = g_bt + (size_t)block_col * K_TOT;

    // per-thread load slots: 4 A chunks + 4 B chunks per stage
    int lrow[4], lkc[4];
    #pragma unroll
    for (int i = 0; i < 4; i++) {
        int f = tid + i * 256;      // [0, 1024)
        lrow[i] = f >> 3;
        lkc[i]  = (f & 7) << 2;
    }

    auto prefetch = [&](int it) {
        const int s  = it % NSTAGE;
        const int k0 = it * BK;
        const uint32_t sa = sbase + s * STAGE_BYTES;
        #pragma unroll
        for (int i = 0; i < 4; i++) {
            uint32_t soff = (uint32_t)(lrow[i] * A_PAD + lkc[i]) * 4;
            cp_async16(sa + soff, gA + (size_t)lrow[i] * K_TOT + k0 + lkc[i]);
            cp_async16(sa + B_IN_STAGE + soff, gB + (size_t)lrow[i] * K_TOT + k0 + lkc[i]);
        }
    };

    float acc[2][8][4];
    #pragma unroll
    for (int mf = 0; mf < 2; mf++)
        #pragma unroll
        for (int nf = 0; nf < 8; nf++)
            #pragma unroll
            for (int e = 0; e < 4; e++) acc[mf][nf][e] = 0.0f;

    prefetch(0); cp_commit();
    prefetch(1); cp_commit();

    for (int it = 0; it < NITER; it++) {
        if (it + 2 < NITER) prefetch(it + 2);
        cp_commit();                 // always commit (empty groups complete instantly)
        cp_wait2();                  // stage `it` resident
        __syncthreads();

        const int s = it % NSTAGE;
        const float* As = reinterpret_cast<const float*>(smem + s * STAGE_BYTES);
        const float* Bs = reinterpret_cast<const float*>(smem + s * STAGE_BYTES + B_IN_STAGE);

        #pragma unroll
        for (int kf = 0; kf < 4; kf++) {
            const int k = kf * 8 + tg;
            uint32_t a[2][4];
            #pragma unroll
            for (int mf = 0; mf < 2; mf++) {
                const float* ap = As + (wm * 32 + mf * 16 + g) * A_PAD + k;
                a[mf][0] = __float_as_uint(ap[0]);
                a[mf][1] = __float_as_uint(ap[8 * A_PAD]);
                a[mf][2] = __float_as_uint(ap[4]);
                a[mf][3] = __float_as_uint(ap[8 * A_PAD + 4]);
            }
            #pragma unroll
            for (int nf = 0; nf < 8; nf++) {
                const float* bp = Bs + (wn * 64 + nf * 8 + g) * A_PAD + k;
                uint32_t b0 = __float_as_uint(bp[0]);
                uint32_t b1 = __float_as_uint(bp[4]);
                mma_tf32(acc[0][nf], a[0], b0, b1);
                mma_tf32(acc[1][nf], a[1], b0, b1);
            }
        }
        __syncthreads();             // stage free before overwrite next iter
    }

    // ---- epilogue: direct float2 stores + t3 ----
    #pragma unroll
    for (int mf = 0; mf < 2; mf++) {
        const int row0 = block_row + wm * 32 + mf * 16 + g;
        #pragma unroll
        for (int nf = 0; nf < 8; nf++) {
            const int col = block_col + wn * 64 + nf * 8 + tg * 2;
            const float t0 = g_t3[col];
            const float t1 = g_t3[col + 1];
            float2 v0 = make_float2(acc[mf][nf][0] + t0, acc[mf][nf][1] + t1);
            float2 v1 = make_float2(acc[mf][nf][2] + t0, acc[mf][nf][3] + t1);
            *reinterpret_cast<float2*>(out + (size_t)row0 * C_DIM + col)       = v0;
            *reinterpret_cast<float2*>(out + (size_t)(row0 + 8) * C_DIM + col) = v1;
        }
    }
}

// ---------------------------------------------------------------------------
extern "C" void kernel_launch(void* const* d_in, const int* in_sizes, int n_in,
                              void* d_out, int out_size) {
    const float* x       = (const float*)d_in[0];   // (8192, 512)
    const float* weight  = (const float*)d_in[1];   // (512, 2048)
    const float* centers = (const float*)d_in[2];   // (2048, 512)
    float* out = (float*)d_out;                     // (8192, 2048)

    static int smem_set = 0;
    if (!smem_set) {
        cudaFuncSetAttribute(rbf_mma_gemm, cudaFuncAttributeMaxDynamicSharedMemorySize,
                             NSTAGE * STAGE_BYTES);
        smem_set = 1;
    }

    dim3 pgrid(I_DIM / 32, C_DIM / 32);
    prep_w_kernel<<<pgrid, dim3(32, 8)>>>(weight, centers);
    t3_reduce_kernel<<<(C_DIM + 255) / 256, 256>>>();
    prep_x_kernel<<<(B_DIM * I_DIM / 4) / 256, 256>>>(x);

    dim3 ggrid(C_DIM / BN, B_DIM / BM);   // (16, 64)
    rbf_mma_gemm<<<ggrid, 256, NSTAGE * STAGE_BYTES>>>(out);
}

// round 4
// speedup vs baseline: 7.5155x; 1.9214x over previous
#include <cuda_runtime.h>
#include <cuda_fp16.h>
#include <cstdint>

#define B_DIM 8192
#define I_DIM 512
#define C_DIM 2048
#define K_TOT 1024          // concatenated K: [x^2 | x]

#define BM 128
#define BN 128
#define BK 64
#define NITER (K_TOT / BK)          // 16
#define NSTAGE 3
#define ROW_PITCH_H 72              // halves per smem row (64 + 8 pad) = 144 B
#define STAGE_A_BYTES (BM * ROW_PITCH_H * 2)       // 18432
#define STAGE_BYTES (2 * STAGE_A_BYTES)            // 36864 (A + B)

// ---------------- device scratch (no allocs allowed) ----------------
__device__ __half g_a [B_DIM * K_TOT];   // [h(x^2) | h(x)]            (8192, 1024)
__device__ __half g_bt[C_DIM * K_TOT];   // [h(w^2) | h(-2 w^2 c)]     (2048, 1024)
__device__ float  g_t3p[16 * C_DIM];
__device__ float  g_t3[C_DIM];

// ---------------- helpers ----------------
__device__ __forceinline__ uint32_t smem_u32(const void* p) {
    uint32_t a;
    asm("{ .reg .u64 t; cvta.to.shared.u64 t, %1; cvt.u32.u64 %0, t; }" : "=r"(a) : "l"(p));
    return a;
}
__device__ __forceinline__ void cp_async16(uint32_t saddr, const void* gaddr) {
    asm volatile("cp.async.cg.shared.global [%0], [%1], 16;" :: "r"(saddr), "l"(gaddr));
}
__device__ __forceinline__ void cp_commit() {
    asm volatile("cp.async.commit_group;" ::: "memory");
}
__device__ __forceinline__ void cp_wait2() {
    asm volatile("cp.async.wait_group 2;" ::: "memory");
}
__device__ __forceinline__ void ldsm_x4(uint32_t* r, uint32_t addr) {
    asm volatile("ldmatrix.sync.aligned.m8n8.x4.shared.b16 {%0,%1,%2,%3}, [%4];"
                 : "=r"(r[0]), "=r"(r[1]), "=r"(r[2]), "=r"(r[3]) : "r"(addr));
}
__device__ __forceinline__ void mma_f16(float* d, const uint32_t* a, uint32_t b0, uint32_t b1) {
    asm volatile(
        "mma.sync.aligned.m16n8k16.row.col.f32.f16.f16.f32 "
        "{%0,%1,%2,%3}, {%4,%5,%6,%7}, {%8,%9}, {%0,%1,%2,%3};"
        : "+f"(d[0]), "+f"(d[1]), "+f"(d[2]), "+f"(d[3])
        : "r"(a[0]), "r"(a[1]), "r"(a[2]), "r"(a[3]), "r"(b0), "r"(b1));
}

// ---------------------------------------------------------------------------
// prep_w: g_bt[c][k] = h(w^2) | h(-2 w^2 centers), + fp32 t3 partials.
// grid (16, 64), block (32, 8).
// ---------------------------------------------------------------------------
__global__ void prep_w_kernel(const float* __restrict__ weight,
                              const float* __restrict__ centers) {
    __shared__ float sW[32][33];
    __shared__ float sC[32][33];

    const int i0 = blockIdx.x * 32;
    const int c0 = blockIdx.y * 32;
    const int tx = threadIdx.x;
    const int ty = threadIdx.y;

    #pragma unroll
    for (int ii = ty; ii < 32; ii += 8)
        sW[ii][tx] = weight[(i0 + ii) * C_DIM + c0 + tx];
    #pragma unroll
    for (int cc = ty; cc < 32; cc += 8)
        sC[cc][tx] = centers[(c0 + cc) * I_DIM + i0 + tx];
    __syncthreads();

    #pragma unroll
    for (int cc = ty; cc < 32; cc += 8) {
        float w  = sW[tx][cc];      // weight[i0+tx][c0+cc]
        float w2 = w * w;
        float ce = sC[cc][tx];      // centers[c0+cc][i0+tx]
        __half* row = g_bt + (size_t)(c0 + cc) * K_TOT;
        row[i0 + tx]         = __float2half_rn(w2);
        row[I_DIM + i0 + tx] = __float2half_rn(-2.0f * w2 * ce);
        float v = w2 * ce * ce;     // exact fp32 t3 partial
        #pragma unroll
        for (int d = 16; d > 0; d >>= 1)
            v += __shfl_xor_sync(0xFFFFFFFF, v, d);
        if (tx == 0) g_t3p[blockIdx.x * C_DIM + c0 + cc] = v;
    }
}

__global__ void t3_reduce_kernel() {
    int c = blockIdx.x * blockDim.x + threadIdx.x;
    if (c < C_DIM) {
        float s = 0.0f;
        #pragma unroll
        for (int p = 0; p < 16; p++) s += g_t3p[p * C_DIM + c];
        g_t3[c] = s;
    }
}

// ---------------------------------------------------------------------------
// prep_x: g_a[b][0:512] = h(x^2), g_a[b][512:1024] = h(x).
// ---------------------------------------------------------------------------
__global__ void prep_x_kernel(const float* __restrict__ x) {
    int f = blockIdx.x * blockDim.x + threadIdx.x;   // float4 id, [0, 1M)
    int r  = f >> 7;                                 // row 0..8191
    int c4 = (f & 127) << 2;                         // col 0..508
    float4 v = *reinterpret_cast<const float4*>(x + (size_t)r * I_DIM + c4);
    __half2 sq0 = __floats2half2_rn(v.x * v.x, v.y * v.y);
    __half2 sq1 = __floats2half2_rn(v.z * v.z, v.w * v.w);
    __half2 rw0 = __floats2half2_rn(v.x, v.y);
    __half2 rw1 = __floats2half2_rn(v.z, v.w);
    __half2* pa = reinterpret_cast<__half2*>(g_a + (size_t)r * K_TOT + c4);
    __half2* pb = reinterpret_cast<__half2*>(g_a + (size_t)r * K_TOT + I_DIM + c4);
    pa[0] = sq0; pa[1] = sq1;
    pb[0] = rw0; pb[1] = rw1;
}

// ---------------------------------------------------------------------------
// GEMM: out = g_a @ g_bt^T + t3.  128x128x64 tiles, 3-stage cp.async,
// 8 warps (4m x 2n), warp tile 32x64, mma m16n8k16 f16 + fp32 accum, ldmatrix.
// ---------------------------------------------------------------------------
__global__ __launch_bounds__(256, 2)
void rbf_mma_gemm(float* __restrict__ out) {
    extern __shared__ char smem[];
    const uint32_t sbase = smem_u32(smem);

    const int tid = threadIdx.x;
    const int wid = tid >> 5;
    const int lid = tid & 31;
    const int g   = lid >> 2;       // groupID 0..7
    const int tg  = lid & 3;        // thread-in-group 0..3
    const int wm  = wid >> 1;       // 0..3  -> m offset wm*32
    const int wn  = wid & 1;        // 0..1  -> n offset wn*64

    const int block_row = blockIdx.y * BM;
    const int block_col = blockIdx.x * BN;
    const __half* gA = g_a  + (size_t)block_row * K_TOT;
    const __half* gB = g_bt + (size_t)block_col * K_TOT;

    // cp.async slots: 4 A + 4 B 16B chunks per thread per stage
    int lrow[4], lkc[4];            // row, k-offset (halves)
    #pragma unroll
    for (int i = 0; i < 4; i++) {
        int f = tid + i * 256;      // [0, 1024)
        lrow[i] = f >> 3;           // 0..127
        lkc[i]  = (f & 7) << 3;     // 0,8,...,56 halves
    }

    auto prefetch = [&](int it) {
        const int s  = it % NSTAGE;
        const int k0 = it * BK;
        const uint32_t sa = sbase + s * STAGE_BYTES;
        #pragma unroll
        for (int i = 0; i < 4; i++) {
            uint32_t soff = (uint32_t)(lrow[i] * ROW_PITCH_H + lkc[i]) * 2;
            cp_async16(sa + soff, gA + (size_t)lrow[i] * K_TOT + k0 + lkc[i]);
            cp_async16(sa + STAGE_A_BYTES + soff, gB + (size_t)lrow[i] * K_TOT + k0 + lkc[i]);
        }
    };

    // ldmatrix per-lane address components
    const int a_row = (lid & 15);             // + m_base
    const int a_kh  = (lid >> 4) << 3;        // 0 or 8 halves, + kf*16
    const int b_row = (lid & 7) + ((lid & 16) >> 1);   // + n_base
    const int b_kh  = (lid & 8);              // 0 or 8 halves, + kf*16

    float acc[2][8][4];
    #pragma unroll
    for (int mf = 0; mf < 2; mf++)
        #pragma unroll
        for (int nf = 0; nf < 8; nf++)
            #pragma unroll
            for (int e = 0; e < 4; e++) acc[mf][nf][e] = 0.0f;

    prefetch(0); cp_commit();
    prefetch(1); cp_commit();

    for (int it = 0; it < NITER; it++) {
        if (it + 2 < NITER) prefetch(it + 2);
        cp_commit();
        cp_wait2();
        __syncthreads();

        const int s = it % NSTAGE;
        const uint32_t aBase = sbase + s * STAGE_BYTES;
        const uint32_t bBase = aBase + STAGE_A_BYTES;

        #pragma unroll
        for (int kf = 0; kf < 4; kf++) {
            uint32_t a[2][4];
            #pragma unroll
            for (int mf = 0; mf < 2; mf++) {
                uint32_t addr = aBase +
                    ((uint32_t)(wm * 32 + mf * 16 + a_row) * ROW_PITCH_H +
                     (uint32_t)(kf * 16 + a_kh)) * 2;
                ldsm_x4(a[mf], addr);
            }
            uint32_t b[4][4];
            #pragma unroll
            for (int np = 0; np < 4; np++) {
                uint32_t addr = bBase +
                    ((uint32_t)(wn * 64 + np * 16 + b_row) * ROW_PITCH_H +
                     (uint32_t)(kf * 16 + b_kh)) * 2;
                ldsm_x4(b[np], addr);
            }
            #pragma unroll
            for (int np = 0; np < 4; np++) {
                mma_f16(acc[0][np * 2 + 0], a[0], b[np][0], b[np][1]);
                mma_f16(acc[1][np * 2 + 0], a[1], b[np][0], b[np][1]);
                mma_f16(acc[0][np * 2 + 1], a[0], b[np][2], b[np][3]);
                mma_f16(acc[1][np * 2 + 1], a[1], b[np][2], b[np][3]);
            }
        }
        __syncthreads();
    }

    // ---- epilogue: direct float2 stores + t3 ----
    #pragma unroll
    for (int mf = 0; mf < 2; mf++) {
        const int row0 = block_row + wm * 32 + mf * 16 + g;
        #pragma unroll
        for (int nf = 0; nf < 8; nf++) {
            const int col = block_col + wn * 64 + nf * 8 + tg * 2;
            const float t0 = g_t3[col];
            const float t1 = g_t3[col + 1];
            float2 v0 = make_float2(acc[mf][nf][0] + t0, acc[mf][nf][1] + t1);
            float2 v1 = make_float2(acc[mf][nf][2] + t0, acc[mf][nf][3] + t1);
            *reinterpret_cast<float2*>(out + (size_t)row0 * C_DIM + col)       = v0;
            *reinterpret_cast<float2*>(out + (size_t)(row0 + 8) * C_DIM + col) = v1;
        }
    }
}

// ---------------------------------------------------------------------------
extern "C" void kernel_launch(void* const* d_in, const int* in_sizes, int n_in,
                              void* d_out, int out_size) {
    const float* x       = (const float*)d_in[0];   // (8192, 512)
    const float* weight  = (const float*)d_in[1];   // (512, 2048)
    const float* centers = (const float*)d_in[2];   // (2048, 512)
    float* out = (float*)d_out;                     // (8192, 2048)

    cudaFuncSetAttribute(rbf_mma_gemm, cudaFuncAttributeMaxDynamicSharedMemorySize,
                         NSTAGE * STAGE_BYTES);

    dim3 pgrid(I_DIM / 32, C_DIM / 32);
    prep_w_kernel<<<pgrid, dim3(32, 8)>>>(weight, centers);
    t3_reduce_kernel<<<(C_DIM + 255) / 256, 256>>>();
    prep_x_kernel<<<(B_DIM * I_DIM / 4) / 256, 256>>>(x);

    dim3 ggrid(C_DIM / BN, B_DIM / BM);   // (16, 64)
    rbf_mma_gemm<<<ggrid, 256, NSTAGE * STAGE_BYTES>>>(out);
}

// round 5
// speedup vs baseline: 7.8790x; 1.0484x over previous
#include <cuda_runtime.h>
#include <cuda_fp16.h>
#include <cstdint>

#define B_DIM 8192
#define I_DIM 512
#define C_DIM 2048
#define K_TOT 1024          // concatenated K: [x^2 | x]

#define BM 128
#define BN 128
#define BK 64
#define NITER (K_TOT / BK)          // 16
#define NSTAGE 3
#define ROW_PITCH_H 72              // halves per smem row (64 + 8 pad) = 144 B
#define STAGE_A_BYTES (BM * ROW_PITCH_H * 2)       // 18432
#define STAGE_BYTES (2 * STAGE_A_BYTES)            // 36864 (A + B)

// ---------------- device scratch (no allocs allowed) ----------------
__device__ __half g_a [B_DIM * K_TOT];   // [h(x^2) | h(x)]            (8192, 1024)
__device__ __half g_bt[C_DIM * K_TOT];   // [h(w^2) | h(-2 w^2 c)]     (2048, 1024)
__device__ float  g_t3p[16 * C_DIM];
__device__ float  g_t3[C_DIM];

// ---------------- helpers ----------------
__device__ __forceinline__ uint32_t smem_u32(const void* p) {
    uint32_t a;
    asm("{ .reg .u64 t; cvta.to.shared.u64 t, %1; cvt.u32.u64 %0, t; }" : "=r"(a) : "l"(p));
    return a;
}
__device__ __forceinline__ void cp_async16(uint32_t saddr, const void* gaddr) {
    asm volatile("cp.async.cg.shared.global [%0], [%1], 16;" :: "r"(saddr), "l"(gaddr));
}
__device__ __forceinline__ void cp_commit() {
    asm volatile("cp.async.commit_group;" ::: "memory");
}
__device__ __forceinline__ void cp_wait1() {
    asm volatile("cp.async.wait_group 1;" ::: "memory");
}
__device__ __forceinline__ void cp_wait0() {
    asm volatile("cp.async.wait_group 0;" ::: "memory");
}
__device__ __forceinline__ void ldsm_x4(uint32_t* r, uint32_t addr) {
    asm volatile("ldmatrix.sync.aligned.m8n8.x4.shared.b16 {%0,%1,%2,%3}, [%4];"
                 : "=r"(r[0]), "=r"(r[1]), "=r"(r[2]), "=r"(r[3]) : "r"(addr));
}
__device__ __forceinline__ void mma_f16(float* d, const uint32_t* a, uint32_t b0, uint32_t b1) {
    asm volatile(
        "mma.sync.aligned.m16n8k16.row.col.f32.f16.f16.f32 "
        "{%0,%1,%2,%3}, {%4,%5,%6,%7}, {%8,%9}, {%0,%1,%2,%3};"
        : "+f"(d[0]), "+f"(d[1]), "+f"(d[2]), "+f"(d[3])
        : "r"(a[0]), "r"(a[1]), "r"(a[2]), "r"(a[3]), "r"(b0), "r"(b1));
}

// ---------------------------------------------------------------------------
// prep_w: g_bt[c][k] = h(w^2) | h(-2 w^2 centers), + fp32 t3 partials.
// ---------------------------------------------------------------------------
__global__ void prep_w_kernel(const float* __restrict__ weight,
                              const float* __restrict__ centers) {
    __shared__ float sW[32][33];
    __shared__ float sC[32][33];

    const int i0 = blockIdx.x * 32;
    const int c0 = blockIdx.y * 32;
    const int tx = threadIdx.x;
    const int ty = threadIdx.y;

    #pragma unroll
    for (int ii = ty; ii < 32; ii += 8)
        sW[ii][tx] = weight[(i0 + ii) * C_DIM + c0 + tx];
    #pragma unroll
    for (int cc = ty; cc < 32; cc += 8)
        sC[cc][tx] = centers[(c0 + cc) * I_DIM + i0 + tx];
    __syncthreads();

    #pragma unroll
    for (int cc = ty; cc < 32; cc += 8) {
        float w  = sW[tx][cc];
        float w2 = w * w;
        float ce = sC[cc][tx];
        __half* row = g_bt + (size_t)(c0 + cc) * K_TOT;
        row[i0 + tx]         = __float2half_rn(w2);
        row[I_DIM + i0 + tx] = __float2half_rn(-2.0f * w2 * ce);
        float v = w2 * ce * ce;
        #pragma unroll
        for (int d = 16; d > 0; d >>= 1)
            v += __shfl_xor_sync(0xFFFFFFFF, v, d);
        if (tx == 0) g_t3p[blockIdx.x * C_DIM + c0 + cc] = v;
    }
}

__global__ void t3_reduce_kernel() {
    int c = blockIdx.x * blockDim.x + threadIdx.x;
    if (c < C_DIM) {
        float s = 0.0f;
        #pragma unroll
        for (int p = 0; p < 16; p++) s += g_t3p[p * C_DIM + c];
        g_t3[c] = s;
    }
}

// ---------------------------------------------------------------------------
// prep_x: g_a[b][0:512] = h(x^2), g_a[b][512:1024] = h(x).
// ---------------------------------------------------------------------------
__global__ void prep_x_kernel(const float* __restrict__ x) {
    int f = blockIdx.x * blockDim.x + threadIdx.x;
    int r  = f >> 7;
    int c4 = (f & 127) << 2;
    float4 v = *reinterpret_cast<const float4*>(x + (size_t)r * I_DIM + c4);
    __half2 sq0 = __floats2half2_rn(v.x * v.x, v.y * v.y);
    __half2 sq1 = __floats2half2_rn(v.z * v.z, v.w * v.w);
    __half2 rw0 = __floats2half2_rn(v.x, v.y);
    __half2 rw1 = __floats2half2_rn(v.z, v.w);
    __half2* pa = reinterpret_cast<__half2*>(g_a + (size_t)r * K_TOT + c4);
    __half2* pb = reinterpret_cast<__half2*>(g_a + (size_t)r * K_TOT + I_DIM + c4);
    pa[0] = sq0; pa[1] = sq1;
    pb[0] = rw0; pb[1] = rw1;
}

// ---------------------------------------------------------------------------
// GEMM: out = g_a @ g_bt^T + t3.  128x128x64 tiles, 3-stage cp.async,
// 8 warps (4m x 2n), warp tile 32x64, m16n8k16 f16/fp32, software-pipelined
// ldmatrix fragments, ONE barrier per k-iteration.
// ---------------------------------------------------------------------------
__global__ __launch_bounds__(256, 2)
void rbf_mma_gemm(float* __restrict__ out) {
    extern __shared__ char smem[];
    const uint32_t sbase = smem_u32(smem);

    const int tid = threadIdx.x;
    const int wid = tid >> 5;
    const int lid = tid & 31;
    const int g   = lid >> 2;
    const int tg  = lid & 3;
    const int wm  = wid >> 1;       // 0..3 -> m offset wm*32
    const int wn  = wid & 1;        // 0..1 -> n offset wn*64

    const int block_row = blockIdx.y * BM;
    const int block_col = blockIdx.x * BN;
    const __half* gA = g_a  + (size_t)block_row * K_TOT;
    const __half* gB = g_bt + (size_t)block_col * K_TOT;

    auto prefetch = [&](int it) {
        const int s  = it % NSTAGE;
        const int k0 = it * BK;
        const uint32_t sa = sbase + s * STAGE_BYTES;
        #pragma unroll
        for (int i = 0; i < 4; i++) {
            int f   = tid + i * 256;
            int row = f >> 3;
            int kc  = (f & 7) << 3;
            uint32_t soff = (uint32_t)(row * ROW_PITCH_H + kc) * 2;
            cp_async16(sa + soff, gA + (size_t)row * K_TOT + k0 + kc);
            cp_async16(sa + STAGE_A_BYTES + soff, gB + (size_t)row * K_TOT + k0 + kc);
        }
    };

    // ldmatrix per-lane address components
    const int a_row = (lid & 15);
    const int a_kh  = (lid >> 4) << 3;
    const int b_row = (lid & 7) + ((lid & 16) >> 1);
    const int b_kh  = (lid & 8);
    const uint32_t a_lane_off = ((uint32_t)(wm * 32 + a_row) * ROW_PITCH_H + a_kh) * 2;
    const uint32_t b_lane_off = ((uint32_t)(wn * 64 + b_row) * ROW_PITCH_H + b_kh) * 2;

    float acc[2][8][4];
    #pragma unroll
    for (int mf = 0; mf < 2; mf++)
        #pragma unroll
        for (int nf = 0; nf < 8; nf++)
            #pragma unroll
            for (int e = 0; e < 4; e++) acc[mf][nf][e] = 0.0f;

    prefetch(0); cp_commit();
    prefetch(1); cp_commit();

    for (int it = 0; it < NITER; it++) {
        if (it == NITER - 1) cp_wait0(); else cp_wait1();
        __syncthreads();
        if (it + 2 < NITER) { prefetch(it + 2); cp_commit(); }

        const int s = it % NSTAGE;
        const uint32_t aBase = sbase + s * STAGE_BYTES + a_lane_off;
        const uint32_t bBase = sbase + s * STAGE_BYTES + STAGE_A_BYTES + b_lane_off;

        // rotated fragment buffers
        uint32_t afr[2][2][4];   // [kf&1][mf][4]
        uint32_t bfr[2][4];      // [np&1][4]

        // preload kf=0 A frags and (kf=0, np=0) B frag
        ldsm_x4(afr[0][0], aBase + 0 * 32);                       // mf=0 (offset 16 rows handled by frag layout)
        ldsm_x4(afr[0][1], aBase + (uint32_t)(16 * ROW_PITCH_H) * 2);
        ldsm_x4(bfr[0],    bBase);

        #pragma unroll
        for (int kf = 0; kf < 4; kf++) {
            const uint32_t akoff = (uint32_t)(kf * 16) * 2;
            #pragma unroll
            for (int np = 0; np < 4; np++) {
                // prefetch next B fragment (np+1, or kf+1/np=0)
                if (!(kf == 3 && np == 3)) {
                    const int nkf = (np == 3) ? kf + 1 : kf;
                    const int nnp = (np == 3) ? 0 : np + 1;
                    ldsm_x4(bfr[(np + 1) & 1],
                            bBase + ((uint32_t)(nnp * 16) * ROW_PITCH_H + (uint32_t)(nkf * 16)) * 2);
                }
                // prefetch next-kf A fragments at np==2 (double-buffered)
                if (np == 2 && kf < 3) {
                    const uint32_t nakoff = (uint32_t)((kf + 1) * 16) * 2;
                    ldsm_x4(afr[(kf + 1) & 1][0], aBase + nakoff);
                    ldsm_x4(afr[(kf + 1) & 1][1],
                            aBase + (uint32_t)(16 * ROW_PITCH_H) * 2 + nakoff);
                }
                const uint32_t* a0 = afr[kf & 1][0];
                const uint32_t* a1 = afr[kf & 1][1];
                const uint32_t* b  = bfr[np & 1];
                mma_f16(acc[0][np * 2 + 0], a0, b[0], b[1]);
                mma_f16(acc[1][np * 2 + 0], a1, b[0], b[1]);
                mma_f16(acc[0][np * 2 + 1], a0, b[2], b[3]);
                mma_f16(acc[1][np * 2 + 1], a1, b[2], b[3]);
            }
            (void)akoff;
        }
    }

    // ---- epilogue: direct float2 stores + t3 ----
    #pragma unroll
    for (int mf = 0; mf < 2; mf++) {
        const int row0 = block_row + wm * 32 + mf * 16 + g;
        #pragma unroll
        for (int nf = 0; nf < 8; nf++) {
            const int col = block_col + wn * 64 + nf * 8 + tg * 2;
            const float t0 = g_t3[col];
            const float t1 = g_t3[col + 1];
            float2 v0 = make_float2(acc[mf][nf][0] + t0, acc[mf][nf][1] + t1);
            float2 v1 = make_float2(acc[mf][nf][2] + t0, acc[mf][nf][3] + t1);
            *reinterpret_cast<float2*>(out + (size_t)row0 * C_DIM + col)       = v0;
            *reinterpret_cast<float2*>(out + (size_t)(row0 + 8) * C_DIM + col) = v1;
        }
    }
}

// ---------------------------------------------------------------------------
extern "C" void kernel_launch(void* const* d_in, const int* in_sizes, int n_in,
                              void* d_out, int out_size) {
    const float* x       = (const float*)d_in[0];   // (8192, 512)
    const float* weight  = (const float*)d_in[1];   // (512, 2048)
    const float* centers = (const float*)d_in[2];   // (2048, 512)
    float* out = (float*)d_out;                     // (8192, 2048)

    cudaFuncSetAttribute(rbf_mma_gemm, cudaFuncAttributeMaxDynamicSharedMemorySize,
                         NSTAGE * STAGE_BYTES);

    dim3 pgrid(I_DIM / 32, C_DIM / 32);
    prep_w_kernel<<<pgrid, dim3(32, 8)>>>(weight, centers);
    t3_reduce_kernel<<<(C_DIM + 255) / 256, 256>>>();
    prep_x_kernel<<<(B_DIM * I_DIM / 4) / 256, 256>>>(x);

    dim3 ggrid(C_DIM / BN, B_DIM / BM);   // (16, 64)
    rbf_mma_gemm<<<ggrid, 256, NSTAGE * STAGE_BYTES>>>(out);
}